// round 14
// baseline (speedup 1.0000x reference)
#include <cuda_runtime.h>
#include <cuda_bf16.h>
#include <cstdint>

#define T_TOK 131072
#define Dd 256
#define NPROTO 512
#define BM 128
#define NBLK (T_TOK / BM)           // 1024
#define TDTOT ((size_t)T_TOK * Dd)  // 33554432
#define TAU 0.35f
#define CAND_CUT 2e-3f
#define FIXB 8
#define MAXC 16

#define ASTR 264                    // g_wbf row stride in bf16 (528B)
#define CHP 32                      // protos per B chunk
#define NCH (NPROTO / CHP)          // 16 chunks
#define CHB (CHP * ASTR * 2)        // 16896 bytes per chunk

// smem byte offsets (A tile REMOVED -> ~38KB total, 3 CTAs/SM)
#define SM_B    0                   // 2 chunks * 16896 = 33792
#define SM_WNS  33792               // 2048
#define SM_RV   35840               // 512
#define SM_R2   36352               // 512
#define SM_RI   36864               // 512
#define SM_IDX  37376               // 512
#define SM_FLG  37888               // 512
#define SMEMB   38400

typedef unsigned int u32;

__device__ float g_wn[NPROTO];
__device__ __align__(16) __nv_bfloat16 g_wbf[NPROTO * ASTR];  // W bf16, tile layout
__device__ __align__(16) float g_wt[Dd * NPROTO];             // W fp32 transposed [k][j]
__device__ float g_partials[NBLK];
__device__ float g_epart[256];
__device__ float g_extra[T_TOK];
__device__ int   g_flaglist[T_TOK];
__device__ int   g_nflag;

__device__ __forceinline__ u32 smem_u32(const void* p) {
    u32 a;
    asm("{ .reg .u64 t; cvta.to.shared.u64 t, %1; cvt.u32.u64 %0, t; }" : "=r"(a) : "l"(p));
    return a;
}
__device__ __forceinline__ void cp16(u32 dst, const void* src) {
    asm volatile("cp.async.ca.shared.global [%0], [%1], 16;" :: "r"(dst), "l"(src));
}
#define CP_COMMIT() asm volatile("cp.async.commit_group;" ::: "memory")
#define CP_WAIT0()  asm volatile("cp.async.wait_group 0;" ::: "memory")

__device__ __forceinline__ void ldm_x4(u32 addr, u32& r0, u32& r1, u32& r2, u32& r3) {
    asm volatile("ldmatrix.sync.aligned.m8n8.x4.shared.b16 {%0,%1,%2,%3}, [%4];"
                 : "=r"(r0), "=r"(r1), "=r"(r2), "=r"(r3) : "r"(addr));
}
__device__ __forceinline__ void mma_bf16(float* d, u32 a0, u32 a1, u32 a2, u32 a3,
                                         u32 b0, u32 b1) {
    asm volatile(
        "mma.sync.aligned.m16n8k16.row.col.f32.bf16.bf16.f32 "
        "{%0,%1,%2,%3}, {%4,%5,%6,%7}, {%8,%9}, {%0,%1,%2,%3};"
        : "+f"(d[0]), "+f"(d[1]), "+f"(d[2]), "+f"(d[3])
        : "r"(a0), "r"(a1), "r"(a2), "r"(a3), "r"(b0), "r"(b1));
}

// Build one m16k16 A fragment directly from global fp32 x (standard mma layout:
// lane g=lane>>2, t=lane&3; a0=A[g][2t..2t+1], a1=A[g+8][..], a2=A[g][2t+8..9],
// a3=A[g+8][2t+8..9]). Same __floats2bfloat162_rn pairing as the old staging
// path -> bit-identical bf16 values.
__device__ __forceinline__ void ldA_gmem(const float* __restrict__ p0,
                                         const float* __restrict__ p8, int koff,
                                         u32& a0, u32& a1, u32& a2, u32& a3) {
    float2 v0 = *(const float2*)(p0 + koff);
    float2 v1 = *(const float2*)(p8 + koff);
    float2 v2 = *(const float2*)(p0 + koff + 8);
    float2 v3 = *(const float2*)(p8 + koff + 8);
    __nv_bfloat162 q0 = __floats2bfloat162_rn(v0.x, v0.y);
    __nv_bfloat162 q1 = __floats2bfloat162_rn(v1.x, v1.y);
    __nv_bfloat162 q2 = __floats2bfloat162_rn(v2.x, v2.y);
    __nv_bfloat162 q3 = __floats2bfloat162_rn(v3.x, v3.y);
    a0 = *(u32*)&q0; a1 = *(u32*)&q1; a2 = *(u32*)&q2; a3 = *(u32*)&q3;
}

// ---- merged: ||w||^2 + bf16 W copy + fp32 W transpose + counter reset ----
__global__ void wnwt_kernel(const float* __restrict__ pw) {
    const int tid = threadIdx.x;
    const int lane = tid & 31;

    // transpose part: every block handles one k
    {
        const int k = blockIdx.x;
        g_wt[(size_t)k * NPROTO + tid]       = pw[(size_t)tid * Dd + k];
        g_wt[(size_t)k * NPROTO + tid + 256] = pw[(size_t)(tid + 256) * Dd + k];
    }
    if (blockIdx.x >= 64) return;
    if (blockIdx.x == 0 && tid == 0) g_nflag = 0;

    // wn + bf16 copy: warp-per-proto, blocks 0..63
    const int j = blockIdx.x * 8 + (tid >> 5);
    const float4* r4 = (const float4*)(pw + (size_t)j * Dd);
    float4 a = r4[lane * 2];
    float4 b = r4[lane * 2 + 1];

    double s = (double)a.x * a.x + (double)a.y * a.y + (double)a.z * a.z + (double)a.w * a.w
             + (double)b.x * b.x + (double)b.y * b.y + (double)b.z * b.z + (double)b.w * b.w;
    #pragma unroll
    for (int off = 16; off > 0; off >>= 1)
        s += __shfl_xor_sync(0xffffffffu, s, off);
    if (lane == 0) g_wn[j] = (float)s;

    __nv_bfloat162 q0 = __floats2bfloat162_rn(a.x, a.y);
    __nv_bfloat162 q1 = __floats2bfloat162_rn(a.z, a.w);
    __nv_bfloat162 q2 = __floats2bfloat162_rn(b.x, b.y);
    __nv_bfloat162 q3 = __floats2bfloat162_rn(b.z, b.w);
    uint4 v;
    v.x = *(u32*)&q0; v.y = *(u32*)&q1; v.z = *(u32*)&q2; v.w = *(u32*)&q3;
    *(uint4*)(g_wbf + (size_t)j * ASTR + lane * 8) = v;
    if (lane == 0) {
        uint4 z = {0u, 0u, 0u, 0u};
        *(uint4*)(g_wbf + (size_t)j * ASTR + Dd) = z;
    }
}

// no-op kernel: keeps the profiler's 4th-launch capture slot on fix_ties
__global__ void dummy_k() {}

__device__ __forceinline__ void upd(float s, int j, float& b1, float& b2, int& i1) {
    if (s < b1) { b2 = b1; b1 = s; i1 = j; }
    else if (s < b2) b2 = s;
}

// ---- main fused kernel: A fragments from gmem (no A smem / no A reg-cache),
//      smem ~38KB + regs<=85 -> 3 CTAs/SM = 24 warps for latency hiding ----
__global__ __launch_bounds__(256, 3) void vq_main(const float* __restrict__ x,
                                                  const float* __restrict__ pw,
                                                  float* __restrict__ out) {
    extern __shared__ char smem[];
    const u32 sb = smem_u32(smem);
    float* wns  = (float*)(smem + SM_WNS);
    float* rv   = (float*)(smem + SM_RV);
    float* r2s  = (float*)(smem + SM_R2);
    int*   ris  = (int*)  (smem + SM_RI);
    int*   idxs = (int*)  (smem + SM_IDX);
    int*   flg  = (int*)  (smem + SM_FLG);

    const int tid = threadIdx.x;
    const int wid = tid >> 5;
    const int lane = tid & 31;
    const int bm = blockIdx.x * BM;

    {
        const char* src = (const char*)g_wbf;
        for (int e = tid; e < CHB / 16; e += 256)
            cp16(sb + SM_B + e * 16, src + e * 16);
        CP_COMMIT();
    }
    for (int e = tid; e < NPROTO; e += 256) wns[e] = g_wn[e];
    CP_WAIT0();
    __syncthreads();

    // A source pointers (per-thread, standard fragment layout)
    const float* xw0 = x + (size_t)(bm + wid * 16 + (lane >> 2)) * Dd + (lane & 3) * 2;
    const float* xw8 = xw0 + 8 * Dd;

    const u32 brow = ((lane >> 4) * 8 + (lane & 7));
    const u32 bkoff = ((lane >> 3) & 1) * 8;

    const int th = lane & 3;
    float b1a = 3.0e38f, b2a = 3.0e38f; int i1a = 0;
    float b1b = 3.0e38f, b2b = 3.0e38f; int i1b = 0;

    for (int c = 0; c < NCH; c++) {
        if (c < NCH - 1) {
            const char* src = (const char*)g_wbf + (size_t)(c + 1) * CHB;
            u32 dst = sb + SM_B + ((c + 1) & 1) * CHB;
            for (int e = tid; e < CHB / 16; e += 256)
                cp16(dst + e * 16, src + e * 16);
            CP_COMMIT();
        }
        float acc[4][4];
        #pragma unroll
        for (int i = 0; i < 4; i++)
            #pragma unroll
            for (int q = 0; q < 4; q++) acc[i][q] = 0.f;

        const u32 bbase = sb + SM_B + (c & 1) * CHB;
        #pragma unroll
        for (int kt = 0; kt < 16; kt++) {
            u32 a0, a1, a2, a3;
            ldA_gmem(xw0, xw8, kt * 16, a0, a1, a2, a3);
            #pragma unroll
            for (int ni = 0; ni < 2; ni++) {
                u32 c0, c1, c2, c3;
                u32 addr = bbase + (((ni * 16 + brow) * ASTR) + kt * 16 + bkoff) * 2;
                ldm_x4(addr, c0, c1, c2, c3);
                mma_bf16(acc[ni * 2],     a0, a1, a2, a3, c0, c1);
                mma_bf16(acc[ni * 2 + 1], a0, a1, a2, a3, c2, c3);
            }
        }
        #pragma unroll
        for (int i = 0; i < 4; i++) {
            const int jb = c * CHP + i * 8 + th * 2;
            float s;
            s = fmaf(-2.f, acc[i][0], wns[jb]);     upd(s, jb,     b1a, b2a, i1a);
            s = fmaf(-2.f, acc[i][1], wns[jb + 1]); upd(s, jb + 1, b1a, b2a, i1a);
            s = fmaf(-2.f, acc[i][2], wns[jb]);     upd(s, jb,     b1b, b2b, i1b);
            s = fmaf(-2.f, acc[i][3], wns[jb + 1]); upd(s, jb + 1, b1b, b2b, i1b);
        }
        if (c < NCH - 1) { CP_WAIT0(); __syncthreads(); }
    }

    #pragma unroll
    for (int off = 1; off <= 2; off <<= 1) {
        float ov, o2; int oi;
        ov = __shfl_xor_sync(0xffffffffu, b1a, off);
        o2 = __shfl_xor_sync(0xffffffffu, b2a, off);
        oi = __shfl_xor_sync(0xffffffffu, i1a, off);
        if (ov < b1a || (ov == b1a && oi < i1a)) { b2a = fminf(b1a, o2); b1a = ov; i1a = oi; }
        else b2a = fminf(b2a, ov);
        ov = __shfl_xor_sync(0xffffffffu, b1b, off);
        o2 = __shfl_xor_sync(0xffffffffu, b2b, off);
        oi = __shfl_xor_sync(0xffffffffu, i1b, off);
        if (ov < b1b || (ov == b1b && oi < i1b)) { b2b = fminf(b1b, o2); b1b = ov; i1b = oi; }
        else b2b = fminf(b2b, ov);
    }
    if (th == 0) {
        int g = lane >> 2;
        int ra = wid * 16 + g, rb = ra + 8;
        rv[ra] = b1a; r2s[ra] = b2a; ris[ra] = i1a;
        rv[rb] = b1b; r2s[rb] = b2b; ris[rb] = i1b;
    }
    __syncthreads();
    if (tid < BM) {
        float B1 = rv[tid], B2 = r2s[tid];
        int I1 = ris[tid];
        idxs[tid] = I1;
        int f = (B2 - B1 < TAU) ? 1 : 0;
        flg[tid] = f;
        if (f) g_flaglist[atomicAdd(&g_nflag, 1)] = bm + tid;
    }
    __syncthreads();

    float lsum = 0.f;
    float4* outP = (float4*)out;
    float4* outX = outP + TDTOT / 4;
    const float4* w4 = (const float4*)pw;
    const float4* x4 = (const float4*)x;
    for (int e = tid; e < BM * 64; e += 256) {
        int r = e >> 6, c4 = e & 63;
        int j = idxs[r];
        float4 wv = __ldg(&w4[(size_t)j * 64 + c4]);
        float4 xv = x4[(size_t)(bm + r) * 64 + c4];
        size_t o = (size_t)(bm + r) * 64 + c4;
        float4 dx;
        dx.x = xv.x - wv.x; dx.y = xv.y - wv.y;
        dx.z = xv.z - wv.z; dx.w = xv.w - wv.w;
        __stcs(&outP[o], wv);
        __stcs(&outX[o], dx);
        if (!flg[r]) lsum += dx.x * dx.x + dx.y * dx.y + dx.z * dx.z + dx.w * dx.w;
    }
    #pragma unroll
    for (int s = 16; s > 0; s >>= 1) lsum += __shfl_down_sync(0xffffffffu, lsum, s);
    __syncthreads();
    if ((tid & 31) == 0) rv[wid] = lsum;
    __syncthreads();
    if (tid == 0) {
        float t = 0.f;
        #pragma unroll
        for (int w = 0; w < 8; w++) t += rv[w];
        g_partials[blockIdx.x] = t;
    }
}

// ---- phase 2: warp-per-token with transposed-W tier-1 (unchanged) ----
__global__ __launch_bounds__(256) void fix_ties(const float* __restrict__ x,
                                                const float* __restrict__ pw,
                                                float* __restrict__ out) {
    __shared__ float xs[FIXB][Dd];
    __shared__ float sc[FIXB][NPROTO];
    __shared__ int clist[FIXB][MAXC];

    const int tid = threadIdx.x;
    const int lane = tid & 31, wrp = tid >> 5;
    const int nf = g_nflag;
    const int nb = (nf + FIXB - 1) / FIXB;

    for (int b = blockIdx.x; b < nb; b += gridDim.x) {
        const int base = b * FIXB;
        const int m = min(FIXB, nf - base);
        __syncthreads();
        for (int e = tid; e < m * Dd; e += 256) {
            int i = e >> 8, k = e & 255;
            xs[i][k] = x[(size_t)g_flaglist[base + i] * Dd + k];
        }
        __syncthreads();

        float a0[FIXB], a1[FIXB];
        #pragma unroll
        for (int i = 0; i < FIXB; i++) { a0[i] = 0.f; a1[i] = 0.f; }
        for (int k4 = 0; k4 < 64; k4++) {
            float4 xv[FIXB];
            #pragma unroll
            for (int i = 0; i < FIXB; i++)
                xv[i] = *(const float4*)&xs[i][k4 * 4];
            #pragma unroll
            for (int q = 0; q < 4; q++) {
                const float* wtk = g_wt + (size_t)(k4 * 4 + q) * NPROTO;
                float w0 = wtk[tid];
                float w1 = wtk[tid + 256];
                #pragma unroll
                for (int i = 0; i < FIXB; i++) {
                    float xq = (q == 0) ? xv[i].x : (q == 1) ? xv[i].y
                             : (q == 2) ? xv[i].z : xv[i].w;
                    a0[i] = fmaf(xq, w0, a0[i]);
                    a1[i] = fmaf(xq, w1, a1[i]);
                }
            }
        }
        float wn0 = g_wn[tid], wn1 = g_wn[tid + 256];
        #pragma unroll
        for (int i = 0; i < FIXB; i++) {
            sc[i][tid] = wn0 - 2.f * a0[i];
            sc[i][tid + 256] = wn1 - 2.f * a1[i];
        }
        __syncthreads();

        if (wrp < m) {
            const int w = wrp;
            float lmin = 3.0e38f;
            #pragma unroll
            for (int q = 0; q < 16; q++)
                lmin = fminf(lmin, sc[w][lane * 16 + q]);
            #pragma unroll
            for (int off = 16; off > 0; off >>= 1)
                lmin = fminf(lmin, __shfl_xor_sync(0xffffffffu, lmin, off));
            const float thresh = lmin + CAND_CUT;

            int cbase = 0;
            #pragma unroll
            for (int q = 0; q < 16; q++) {
                int j = lane * 16 + q;
                bool pred = sc[w][j] < thresh;
                u32 mask = __ballot_sync(0xffffffffu, pred);
                if (pred) {
                    int pos = cbase + __popc(mask & ((1u << lane) - 1u));
                    if (pos < MAXC) clist[w][pos] = j;
                }
                cbase += __popc(mask);
            }
            const int nc = min(cbase, MAXC);
            __syncwarp();

            double px = 0.0;
            #pragma unroll
            for (int e = 0; e < 8; e++) {
                double v = (double)xs[w][lane * 8 + e];
                px += v * v;
            }
            #pragma unroll
            for (int off = 16; off > 0; off >>= 1)
                px += __shfl_xor_sync(0xffffffffu, px, off);
            const float sx = (float)px;

            float bv = 3.0e38f; int bj = 0x7fffffff;
            for (int c = 0; c < nc; c++) {
                int j = clist[w][c];
                const float* wr = pw + (size_t)j * Dd;
                double d = 0.0;
                #pragma unroll
                for (int e = 0; e < 8; e++)
                    d += (double)xs[w][lane + 32 * e] * (double)wr[lane + 32 * e];
                #pragma unroll
                for (int off = 16; off > 0; off >>= 1)
                    d += __shfl_xor_sync(0xffffffffu, d, off);
                float dist = __fsub_rn(__fadd_rn(sx, g_wn[j]), 2.0f * (float)d);
                if (dist < bv || (dist == bv && j < bj)) { bv = dist; bj = j; }
            }
            const int jb = (nc > 0) ? bj : 0;

            const int t = g_flaglist[base + w];
            float ls = 0.f;
            for (int e = lane; e < Dd; e += 32) {
                float wv = pw[(size_t)jb * Dd + e];
                float xv2 = xs[w][e];
                out[(size_t)t * Dd + e] = wv;
                float dx = xv2 - wv;
                out[TDTOT + (size_t)t * Dd + e] = dx;
                ls += dx * dx;
            }
            #pragma unroll
            for (int off = 16; off > 0; off >>= 1)
                ls += __shfl_xor_sync(0xffffffffu, ls, off);
            if (lane == 0) g_extra[t] = ls;
        }
    }
}

__global__ void reduce_extra() {
    __shared__ float s[256];
    int tid = threadIdx.x;
    int base = blockIdx.x * 512;
    s[tid] = g_extra[base + tid] + g_extra[base + 256 + tid];
    __syncthreads();
    for (int st = 128; st > 0; st >>= 1) {
        if (tid < st) s[tid] += s[tid + st];
        __syncthreads();
    }
    if (tid == 0) g_epart[blockIdx.x] = s[0];
}

__global__ void finalize_loss(float* __restrict__ out) {
    __shared__ float s[256];
    int tid = threadIdx.x;
    float v = 0.f;
    for (int t = tid; t < NBLK; t += 256) v += g_partials[t];
    if (tid < 256) v += g_epart[tid];
    s[tid] = v;
    __syncthreads();
    for (int st = 128; st > 0; st >>= 1) {
        if (tid < st) s[tid] += s[tid + st];
        __syncthreads();
    }
    if (tid == 0) out[2 * TDTOT] = s[0] * (1.25f / (float)TDTOT);
}

extern "C" void kernel_launch(void* const* d_in, const int* in_sizes, int n_in,
                              void* d_out, int out_size) {
    const float* x  = (const float*)d_in[0];
    const float* pw = (const float*)d_in[1];
    float* out = (float*)d_out;

    cudaFuncSetAttribute(vq_main, cudaFuncAttributeMaxDynamicSharedMemorySize, SMEMB);
    wnwt_kernel<<<256, 256>>>(pw);
    dummy_k<<<1, 32>>>();      // capture slot = 4th launch -> fix_ties
    vq_main<<<NBLK, 256, SMEMB>>>(x, pw, out);
    fix_ties<<<512, 256>>>(x, pw, out);
    reduce_extra<<<256, 256>>>();
    finalize_loss<<<1, 256>>>(out);
}

// round 15
// speedup vs baseline: 1.6038x; 1.6038x over previous
#include <cuda_runtime.h>
#include <cuda_bf16.h>
#include <cstdint>

#define T_TOK 131072
#define Dd 256
#define NPROTO 512
#define BM 128
#define NBLK (T_TOK / BM)           // 1024
#define TDTOT ((size_t)T_TOK * Dd)  // 33554432
#define TAU 0.35f
#define CAND_CUT 2e-3f
#define FIXB 4
#define MAXC 16

#define ASTR 264                    // g_wbf row stride in bf16 (528B)
#define CHP 32                      // protos per B chunk
#define NCH (NPROTO / CHP)          // 16 chunks
#define CHB (CHP * ASTR * 2)        // 16896 bytes per chunk

// smem byte offsets (round-13 champion layout)
#define SM_A    0                   // 128*528 = 67584
#define SM_B    67584               // 2 chunks * 16896 = 33792
#define SM_WNS  101376              // 2048
#define SM_RV   103424              // 512
#define SM_R2   103936              // 512
#define SM_RI   104448              // 512
#define SM_IDX  104960              // 512
#define SM_FLG  105472              // 512
#define SMEMB   105984

typedef unsigned int u32;

__device__ float g_wn[NPROTO];
__device__ __align__(16) __nv_bfloat16 g_wbf[NPROTO * ASTR];  // W bf16, tile layout
__device__ __align__(16) float4 g_wt4[(Dd / 4) * NPROTO];     // W fp32: [k4][j] = W[j][4k4..+3]
__device__ float g_partials[NBLK];
__device__ float g_epart[256];
__device__ float g_extra[T_TOK];
__device__ int   g_flaglist[T_TOK];
__device__ int   g_nflag;

__device__ __forceinline__ u32 smem_u32(const void* p) {
    u32 a;
    asm("{ .reg .u64 t; cvta.to.shared.u64 t, %1; cvt.u32.u64 %0, t; }" : "=r"(a) : "l"(p));
    return a;
}
__device__ __forceinline__ void cp16(u32 dst, const void* src) {
    asm volatile("cp.async.ca.shared.global [%0], [%1], 16;" :: "r"(dst), "l"(src));
}
#define CP_COMMIT() asm volatile("cp.async.commit_group;" ::: "memory")
#define CP_WAIT0()  asm volatile("cp.async.wait_group 0;" ::: "memory")

__device__ __forceinline__ void ldm_x4(u32 addr, u32& r0, u32& r1, u32& r2, u32& r3) {
    asm volatile("ldmatrix.sync.aligned.m8n8.x4.shared.b16 {%0,%1,%2,%3}, [%4];"
                 : "=r"(r0), "=r"(r1), "=r"(r2), "=r"(r3) : "r"(addr));
}
__device__ __forceinline__ void mma_bf16(float* d, u32 a0, u32 a1, u32 a2, u32 a3,
                                         u32 b0, u32 b1) {
    asm volatile(
        "mma.sync.aligned.m16n8k16.row.col.f32.bf16.bf16.f32 "
        "{%0,%1,%2,%3}, {%4,%5,%6,%7}, {%8,%9}, {%0,%1,%2,%3};"
        : "+f"(d[0]), "+f"(d[1]), "+f"(d[2]), "+f"(d[3])
        : "r"(a0), "r"(a1), "r"(a2), "r"(a3), "r"(b0), "r"(b1));
}

// Stage a 128x256 fp32 tile as bf16 rows (stride ASTR) into smem.
__device__ __forceinline__ void stage_bf16(__nv_bfloat16* dst, const float4* __restrict__ s4,
                                           size_t row0, int tid) {
    for (int e = tid; e < 4096; e += 256) {
        int r = e >> 5, c8 = e & 31;
        const float4* p = s4 + (row0 + r) * 64 + c8 * 2;
        float4 a = p[0], b = p[1];
        __nv_bfloat162 q0 = __floats2bfloat162_rn(a.x, a.y);
        __nv_bfloat162 q1 = __floats2bfloat162_rn(a.z, a.w);
        __nv_bfloat162 q2 = __floats2bfloat162_rn(b.x, b.y);
        __nv_bfloat162 q3 = __floats2bfloat162_rn(b.z, b.w);
        uint4 v;
        v.x = *(u32*)&q0; v.y = *(u32*)&q1; v.z = *(u32*)&q2; v.w = *(u32*)&q3;
        *(uint4*)(dst + r * ASTR + c8 * 8) = v;
    }
}

// ---- merged: ||w||^2 + bf16 W copy + W float4-repack + counter reset ----
__global__ void wnwt_kernel(const float* __restrict__ pw) {
    const int tid = threadIdx.x;
    const int lane = tid & 31;

    // repack part: block b handles k4 = b (64 blocks); thread j writes protos j, j+256
    if (blockIdx.x < 64) {
        const int k4 = blockIdx.x;
        const float* r0 = pw + (size_t)tid * Dd + k4 * 4;
        const float* r1 = pw + (size_t)(tid + 256) * Dd + k4 * 4;
        g_wt4[(size_t)k4 * NPROTO + tid]       = make_float4(r0[0], r0[1], r0[2], r0[3]);
        g_wt4[(size_t)k4 * NPROTO + tid + 256] = make_float4(r1[0], r1[1], r1[2], r1[3]);
    }
    if (blockIdx.x >= 64) return;
    if (blockIdx.x == 0 && tid == 0) g_nflag = 0;

    // wn + bf16 copy: warp-per-proto, blocks 0..63
    const int j = blockIdx.x * 8 + (tid >> 5);
    const float4* r4 = (const float4*)(pw + (size_t)j * Dd);
    float4 a = r4[lane * 2];
    float4 b = r4[lane * 2 + 1];

    double s = (double)a.x * a.x + (double)a.y * a.y + (double)a.z * a.z + (double)a.w * a.w
             + (double)b.x * b.x + (double)b.y * b.y + (double)b.z * b.z + (double)b.w * b.w;
    #pragma unroll
    for (int off = 16; off > 0; off >>= 1)
        s += __shfl_xor_sync(0xffffffffu, s, off);
    if (lane == 0) g_wn[j] = (float)s;

    __nv_bfloat162 q0 = __floats2bfloat162_rn(a.x, a.y);
    __nv_bfloat162 q1 = __floats2bfloat162_rn(a.z, a.w);
    __nv_bfloat162 q2 = __floats2bfloat162_rn(b.x, b.y);
    __nv_bfloat162 q3 = __floats2bfloat162_rn(b.z, b.w);
    uint4 v;
    v.x = *(u32*)&q0; v.y = *(u32*)&q1; v.z = *(u32*)&q2; v.w = *(u32*)&q3;
    *(uint4*)(g_wbf + (size_t)j * ASTR + lane * 8) = v;
    if (lane == 0) {
        uint4 z = {0u, 0u, 0u, 0u};
        *(uint4*)(g_wbf + (size_t)j * ASTR + Dd) = z;
    }
}

// no-op kernel: keeps the profiler's 4th-launch capture slot on fix_ties
__global__ void dummy_k() {}

__device__ __forceinline__ void upd(float s, int j, float& b1, float& b2, int& i1) {
    if (s < b1) { b2 = b1; b1 = s; i1 = j; }
    else if (s < b2) b2 = s;
}

// ---- main fused kernel (EXACT revert to round-13 champion: A smem + A reg
//      cache, 2 CTAs/SM, streaming-store epilogue) ----
__global__ __launch_bounds__(256, 2) void vq_main(const float* __restrict__ x,
                                                  const float* __restrict__ pw,
                                                  float* __restrict__ out) {
    extern __shared__ char smem[];
    const u32 sb = smem_u32(smem);
    float* wns  = (float*)(smem + SM_WNS);
    float* rv   = (float*)(smem + SM_RV);
    float* r2s  = (float*)(smem + SM_R2);
    int*   ris  = (int*)  (smem + SM_RI);
    int*   idxs = (int*)  (smem + SM_IDX);
    int*   flg  = (int*)  (smem + SM_FLG);

    const int tid = threadIdx.x;
    const int wid = tid >> 5;
    const int lane = tid & 31;
    const int bm = blockIdx.x * BM;

    {
        const char* src = (const char*)g_wbf;
        for (int e = tid; e < CHB / 16; e += 256)
            cp16(sb + SM_B + e * 16, src + e * 16);
        CP_COMMIT();
    }
    for (int e = tid; e < NPROTO; e += 256) wns[e] = g_wn[e];
    stage_bf16((__nv_bfloat16*)(smem + SM_A), (const float4*)x, (size_t)bm, tid);
    CP_WAIT0();
    __syncthreads();

    const u32 arow = wid * 16 + ((lane >> 3) & 1) * 8 + (lane & 7);
    const u32 akoff = (lane >> 4) * 8;
    const u32 brow = ((lane >> 4) * 8 + (lane & 7));
    const u32 bkoff = ((lane >> 3) & 1) * 8;

    u32 A[16][4];
    #pragma unroll
    for (int kt = 0; kt < 16; kt++)
        ldm_x4(sb + SM_A + (arow * ASTR + kt * 16 + akoff) * 2,
               A[kt][0], A[kt][1], A[kt][2], A[kt][3]);

    const int th = lane & 3;
    float b1a = 3.0e38f, b2a = 3.0e38f; int i1a = 0;
    float b1b = 3.0e38f, b2b = 3.0e38f; int i1b = 0;

    for (int c = 0; c < NCH; c++) {
        if (c < NCH - 1) {
            const char* src = (const char*)g_wbf + (size_t)(c + 1) * CHB;
            u32 dst = sb + SM_B + ((c + 1) & 1) * CHB;
            for (int e = tid; e < CHB / 16; e += 256)
                cp16(dst + e * 16, src + e * 16);
            CP_COMMIT();
        }
        float acc[4][4];
        #pragma unroll
        for (int i = 0; i < 4; i++)
            #pragma unroll
            for (int q = 0; q < 4; q++) acc[i][q] = 0.f;

        const u32 bbase = sb + SM_B + (c & 1) * CHB;
        #pragma unroll
        for (int kt = 0; kt < 16; kt++) {
            #pragma unroll
            for (int ni = 0; ni < 2; ni++) {
                u32 c0, c1, c2, c3;
                u32 addr = bbase + (((ni * 16 + brow) * ASTR) + kt * 16 + bkoff) * 2;
                ldm_x4(addr, c0, c1, c2, c3);
                mma_bf16(acc[ni * 2],     A[kt][0], A[kt][1], A[kt][2], A[kt][3], c0, c1);
                mma_bf16(acc[ni * 2 + 1], A[kt][0], A[kt][1], A[kt][2], A[kt][3], c2, c3);
            }
        }
        #pragma unroll
        for (int i = 0; i < 4; i++) {
            const int jb = c * CHP + i * 8 + th * 2;
            float s;
            s = fmaf(-2.f, acc[i][0], wns[jb]);     upd(s, jb,     b1a, b2a, i1a);
            s = fmaf(-2.f, acc[i][1], wns[jb + 1]); upd(s, jb + 1, b1a, b2a, i1a);
            s = fmaf(-2.f, acc[i][2], wns[jb]);     upd(s, jb,     b1b, b2b, i1b);
            s = fmaf(-2.f, acc[i][3], wns[jb + 1]); upd(s, jb + 1, b1b, b2b, i1b);
        }
        if (c < NCH - 1) { CP_WAIT0(); __syncthreads(); }
    }

    #pragma unroll
    for (int off = 1; off <= 2; off <<= 1) {
        float ov, o2; int oi;
        ov = __shfl_xor_sync(0xffffffffu, b1a, off);
        o2 = __shfl_xor_sync(0xffffffffu, b2a, off);
        oi = __shfl_xor_sync(0xffffffffu, i1a, off);
        if (ov < b1a || (ov == b1a && oi < i1a)) { b2a = fminf(b1a, o2); b1a = ov; i1a = oi; }
        else b2a = fminf(b2a, ov);
        ov = __shfl_xor_sync(0xffffffffu, b1b, off);
        o2 = __shfl_xor_sync(0xffffffffu, b2b, off);
        oi = __shfl_xor_sync(0xffffffffu, i1b, off);
        if (ov < b1b || (ov == b1b && oi < i1b)) { b2b = fminf(b1b, o2); b1b = ov; i1b = oi; }
        else b2b = fminf(b2b, ov);
    }
    if (th == 0) {
        int g = lane >> 2;
        int ra = wid * 16 + g, rb = ra + 8;
        rv[ra] = b1a; r2s[ra] = b2a; ris[ra] = i1a;
        rv[rb] = b1b; r2s[rb] = b2b; ris[rb] = i1b;
    }
    __syncthreads();
    if (tid < BM) {
        float B1 = rv[tid], B2 = r2s[tid];
        int I1 = ris[tid];
        idxs[tid] = I1;
        int f = (B2 - B1 < TAU) ? 1 : 0;
        flg[tid] = f;
        if (f) g_flaglist[atomicAdd(&g_nflag, 1)] = bm + tid;
    }
    __syncthreads();

    float lsum = 0.f;
    float4* outP = (float4*)out;
    float4* outX = outP + TDTOT / 4;
    const float4* w4 = (const float4*)pw;
    const float4* x4 = (const float4*)x;
    for (int e = tid; e < BM * 64; e += 256) {
        int r = e >> 6, c4 = e & 63;
        int j = idxs[r];
        float4 wv = __ldg(&w4[(size_t)j * 64 + c4]);
        float4 xv = x4[(size_t)(bm + r) * 64 + c4];
        size_t o = (size_t)(bm + r) * 64 + c4;
        float4 dx;
        dx.x = xv.x - wv.x; dx.y = xv.y - wv.y;
        dx.z = xv.z - wv.z; dx.w = xv.w - wv.w;
        __stcs(&outP[o], wv);
        __stcs(&outX[o], dx);
        if (!flg[r]) lsum += dx.x * dx.x + dx.y * dx.y + dx.z * dx.z + dx.w * dx.w;
    }
    #pragma unroll
    for (int s = 16; s > 0; s >>= 1) lsum += __shfl_down_sync(0xffffffffu, lsum, s);
    __syncthreads();
    if ((tid & 31) == 0) rv[wid] = lsum;
    __syncthreads();
    if (tid == 0) {
        float t = 0.f;
        #pragma unroll
        for (int w = 0; w < 8; w++) t += rv[w];
        g_partials[blockIdx.x] = t;
    }
}

// ---- phase 2: warp-per-token; tier-1 reads float4-packed W (coalesced),
//      FIXB=4 halves per-thread work and doubles block parallelism ----
__global__ __launch_bounds__(256) void fix_ties(const float* __restrict__ x,
                                                const float* __restrict__ pw,
                                                float* __restrict__ out) {
    __shared__ float xs[FIXB][Dd];
    __shared__ float sc[FIXB][NPROTO];
    __shared__ int clist[FIXB][MAXC];

    const int tid = threadIdx.x;
    const int lane = tid & 31, wrp = tid >> 5;
    const int nf = g_nflag;
    const int nb = (nf + FIXB - 1) / FIXB;

    for (int b = blockIdx.x; b < nb; b += gridDim.x) {
        const int base = b * FIXB;
        const int m = min(FIXB, nf - base);
        __syncthreads();
        for (int e = tid; e < m * Dd; e += 256) {
            int i = e >> 8, k = e & 255;
            xs[i][k] = x[(size_t)g_flaglist[base + i] * Dd + k];
        }
        __syncthreads();

        // tier-1: thread t scores protos t, t+256; W via g_wt4[k4][j]
        // (coalesced float4). k-ascending accumulation — bit-identical scores.
        float a0[FIXB], a1[FIXB];
        #pragma unroll
        for (int i = 0; i < FIXB; i++) { a0[i] = 0.f; a1[i] = 0.f; }
        for (int k4 = 0; k4 < 64; k4++) {
            float4 w0 = g_wt4[(size_t)k4 * NPROTO + tid];
            float4 w1 = g_wt4[(size_t)k4 * NPROTO + tid + 256];
            #pragma unroll
            for (int i = 0; i < FIXB; i++) {
                float4 xv = *(const float4*)&xs[i][k4 * 4];
                a0[i] = fmaf(xv.x, w0.x, a0[i]);
                a0[i] = fmaf(xv.y, w0.y, a0[i]);
                a0[i] = fmaf(xv.z, w0.z, a0[i]);
                a0[i] = fmaf(xv.w, w0.w, a0[i]);
                a1[i] = fmaf(xv.x, w1.x, a1[i]);
                a1[i] = fmaf(xv.y, w1.y, a1[i]);
                a1[i] = fmaf(xv.z, w1.z, a1[i]);
                a1[i] = fmaf(xv.w, w1.w, a1[i]);
            }
        }
        float wn0 = g_wn[tid], wn1 = g_wn[tid + 256];
        #pragma unroll
        for (int i = 0; i < FIXB; i++) {
            sc[i][tid] = wn0 - 2.f * a0[i];
            sc[i][tid + 256] = wn1 - 2.f * a1[i];
        }
        __syncthreads();

        // warp w resolves token w — fully warp-local
        if (wrp < m) {
            const int w = wrp;
            float lmin = 3.0e38f;
            #pragma unroll
            for (int q = 0; q < 16; q++)
                lmin = fminf(lmin, sc[w][lane * 16 + q]);
            #pragma unroll
            for (int off = 16; off > 0; off >>= 1)
                lmin = fminf(lmin, __shfl_xor_sync(0xffffffffu, lmin, off));
            const float thresh = lmin + CAND_CUT;

            int cbase = 0;
            #pragma unroll
            for (int q = 0; q < 16; q++) {
                int j = lane * 16 + q;
                bool pred = sc[w][j] < thresh;
                u32 mask = __ballot_sync(0xffffffffu, pred);
                if (pred) {
                    int pos = cbase + __popc(mask & ((1u << lane) - 1u));
                    if (pos < MAXC) clist[w][pos] = j;
                }
                cbase += __popc(mask);
            }
            const int nc = min(cbase, MAXC);
            __syncwarp();

            double px = 0.0;
            #pragma unroll
            for (int e = 0; e < 8; e++) {
                double v = (double)xs[w][lane * 8 + e];
                px += v * v;
            }
            #pragma unroll
            for (int off = 16; off > 0; off >>= 1)
                px += __shfl_xor_sync(0xffffffffu, px, off);
            const float sx = (float)px;

            float bv = 3.0e38f; int bj = 0x7fffffff;
            for (int c = 0; c < nc; c++) {
                int j = clist[w][c];
                const float* wr = pw + (size_t)j * Dd;
                double d = 0.0;
                #pragma unroll
                for (int e = 0; e < 8; e++)
                    d += (double)xs[w][lane + 32 * e] * (double)wr[lane + 32 * e];
                #pragma unroll
                for (int off = 16; off > 0; off >>= 1)
                    d += __shfl_xor_sync(0xffffffffu, d, off);
                float dist = __fsub_rn(__fadd_rn(sx, g_wn[j]), 2.0f * (float)d);
                if (dist < bv || (dist == bv && j < bj)) { bv = dist; bj = j; }
            }
            const int jb = (nc > 0) ? bj : 0;

            const int t = g_flaglist[base + w];
            float ls = 0.f;
            for (int e = lane; e < Dd; e += 32) {
                float wv = pw[(size_t)jb * Dd + e];
                float xv2 = xs[w][e];
                out[(size_t)t * Dd + e] = wv;
                float dx = xv2 - wv;
                out[TDTOT + (size_t)t * Dd + e] = dx;
                ls += dx * dx;
            }
            #pragma unroll
            for (int off = 16; off > 0; off >>= 1)
                ls += __shfl_xor_sync(0xffffffffu, ls, off);
            if (lane == 0) g_extra[t] = ls;
        }
    }
}

__global__ void reduce_extra() {
    __shared__ float s[256];
    int tid = threadIdx.x;
    int base = blockIdx.x * 512;
    s[tid] = g_extra[base + tid] + g_extra[base + 256 + tid];
    __syncthreads();
    for (int st = 128; st > 0; st >>= 1) {
        if (tid < st) s[tid] += s[tid + st];
        __syncthreads();
    }
    if (tid == 0) g_epart[blockIdx.x] = s[0];
}

__global__ void finalize_loss(float* __restrict__ out) {
    __shared__ float s[256];
    int tid = threadIdx.x;
    float v = 0.f;
    for (int t = tid; t < NBLK; t += 256) v += g_partials[t];
    if (tid < 256) v += g_epart[tid];
    s[tid] = v;
    __syncthreads();
    for (int st = 128; st > 0; st >>= 1) {
        if (tid < st) s[tid] += s[tid + st];
        __syncthreads();
    }
    if (tid == 0) out[2 * TDTOT] = s[0] * (1.25f / (float)TDTOT);
}

extern "C" void kernel_launch(void* const* d_in, const int* in_sizes, int n_in,
                              void* d_out, int out_size) {
    const float* x  = (const float*)d_in[0];
    const float* pw = (const float*)d_in[1];
    float* out = (float*)d_out;

    cudaFuncSetAttribute(vq_main, cudaFuncAttributeMaxDynamicSharedMemorySize, SMEMB);
    wnwt_kernel<<<64, 256>>>(pw);
    dummy_k<<<1, 32>>>();      // capture slot = 4th launch -> fix_ties
    vq_main<<<NBLK, 256, SMEMB>>>(x, pw, out);
    fix_ties<<<1024, 256>>>(x, pw, out);
    reduce_extra<<<256, 256>>>();
    finalize_loss<<<1, 256>>>(out);
}

// round 16
// speedup vs baseline: 1.7268x; 1.0767x over previous
#include <cuda_runtime.h>
#include <cuda_bf16.h>
#include <cstdint>

#define T_TOK 131072
#define Dd 256
#define NPROTO 512
#define BM 128
#define NBLK (T_TOK / BM)           // 1024
#define TDTOT ((size_t)T_TOK * Dd)  // 33554432
#define TAU 0.35f
#define CAND_CUT 2e-3f
#define FIXB 8
#define MAXC 16

#define ASTR 264                    // g_wbf row stride in bf16 (528B)
#define CHP 32                      // protos per B chunk
#define NCH (NPROTO / CHP)          // 16 chunks
#define CHB (CHP * ASTR * 2)        // 16896 bytes per chunk

// smem byte offsets (round-13 champion layout)
#define SM_A    0                   // 128*528 = 67584
#define SM_B    67584               // 2 chunks * 16896 = 33792
#define SM_WNS  101376              // 2048
#define SM_RV   103424              // 512
#define SM_R2   103936              // 512
#define SM_RI   104448              // 512
#define SM_IDX  104960              // 512
#define SM_FLG  105472              // 512
#define SMEMB   105984

typedef unsigned int u32;

__device__ float g_wn[NPROTO];
__device__ __align__(16) __nv_bfloat16 g_wbf[NPROTO * ASTR];  // W bf16, tile layout
__device__ __align__(16) float4 g_wt4[(Dd / 4) * NPROTO];     // W fp32: [k4][j] = W[j][4k4..+3]
__device__ float g_partials[NBLK];
__device__ float g_epart[256];
__device__ float g_extra[T_TOK];
__device__ int   g_flaglist[T_TOK];
__device__ int   g_nflag;

__device__ __forceinline__ u32 smem_u32(const void* p) {
    u32 a;
    asm("{ .reg .u64 t; cvta.to.shared.u64 t, %1; cvt.u32.u64 %0, t; }" : "=r"(a) : "l"(p));
    return a;
}
__device__ __forceinline__ void cp16(u32 dst, const void* src) {
    asm volatile("cp.async.ca.shared.global [%0], [%1], 16;" :: "r"(dst), "l"(src));
}
#define CP_COMMIT() asm volatile("cp.async.commit_group;" ::: "memory")
#define CP_WAIT0()  asm volatile("cp.async.wait_group 0;" ::: "memory")

__device__ __forceinline__ void ldm_x4(u32 addr, u32& r0, u32& r1, u32& r2, u32& r3) {
    asm volatile("ldmatrix.sync.aligned.m8n8.x4.shared.b16 {%0,%1,%2,%3}, [%4];"
                 : "=r"(r0), "=r"(r1), "=r"(r2), "=r"(r3) : "r"(addr));
}
__device__ __forceinline__ void mma_bf16(float* d, u32 a0, u32 a1, u32 a2, u32 a3,
                                         u32 b0, u32 b1) {
    asm volatile(
        "mma.sync.aligned.m16n8k16.row.col.f32.bf16.bf16.f32 "
        "{%0,%1,%2,%3}, {%4,%5,%6,%7}, {%8,%9}, {%0,%1,%2,%3};"
        : "+f"(d[0]), "+f"(d[1]), "+f"(d[2]), "+f"(d[3])
        : "r"(a0), "r"(a1), "r"(a2), "r"(a3), "r"(b0), "r"(b1));
}

// Stage a 128x256 fp32 tile as bf16 rows (stride ASTR) into smem.
__device__ __forceinline__ void stage_bf16(__nv_bfloat16* dst, const float4* __restrict__ s4,
                                           size_t row0, int tid) {
    for (int e = tid; e < 4096; e += 256) {
        int r = e >> 5, c8 = e & 31;
        const float4* p = s4 + (row0 + r) * 64 + c8 * 2;
        float4 a = p[0], b = p[1];
        __nv_bfloat162 q0 = __floats2bfloat162_rn(a.x, a.y);
        __nv_bfloat162 q1 = __floats2bfloat162_rn(a.z, a.w);
        __nv_bfloat162 q2 = __floats2bfloat162_rn(b.x, b.y);
        __nv_bfloat162 q3 = __floats2bfloat162_rn(b.z, b.w);
        uint4 v;
        v.x = *(u32*)&q0; v.y = *(u32*)&q1; v.z = *(u32*)&q2; v.w = *(u32*)&q3;
        *(uint4*)(dst + r * ASTR + c8 * 8) = v;
    }
}

// ---- merged: ||w||^2 + bf16 W copy + W float4-repack + counter reset ----
__global__ void wnwt_kernel(const float* __restrict__ pw) {
    const int tid = threadIdx.x;
    const int lane = tid & 31;

    // repack part: block b handles k4 = b (blocks 0..63)
    {
        const int k4 = blockIdx.x;
        const float* r0 = pw + (size_t)tid * Dd + k4 * 4;
        const float* r1 = pw + (size_t)(tid + 256) * Dd + k4 * 4;
        g_wt4[(size_t)k4 * NPROTO + tid]       = make_float4(r0[0], r0[1], r0[2], r0[3]);
        g_wt4[(size_t)k4 * NPROTO + tid + 256] = make_float4(r1[0], r1[1], r1[2], r1[3]);
    }
    if (blockIdx.x == 0 && tid == 0) g_nflag = 0;

    // wn + bf16 copy: warp-per-proto
    const int j = blockIdx.x * 8 + (tid >> 5);
    const float4* r4 = (const float4*)(pw + (size_t)j * Dd);
    float4 a = r4[lane * 2];
    float4 b = r4[lane * 2 + 1];

    double s = (double)a.x * a.x + (double)a.y * a.y + (double)a.z * a.z + (double)a.w * a.w
             + (double)b.x * b.x + (double)b.y * b.y + (double)b.z * b.z + (double)b.w * b.w;
    #pragma unroll
    for (int off = 16; off > 0; off >>= 1)
        s += __shfl_xor_sync(0xffffffffu, s, off);
    if (lane == 0) g_wn[j] = (float)s;

    __nv_bfloat162 q0 = __floats2bfloat162_rn(a.x, a.y);
    __nv_bfloat162 q1 = __floats2bfloat162_rn(a.z, a.w);
    __nv_bfloat162 q2 = __floats2bfloat162_rn(b.x, b.y);
    __nv_bfloat162 q3 = __floats2bfloat162_rn(b.z, b.w);
    uint4 v;
    v.x = *(u32*)&q0; v.y = *(u32*)&q1; v.z = *(u32*)&q2; v.w = *(u32*)&q3;
    *(uint4*)(g_wbf + (size_t)j * ASTR + lane * 8) = v;
    if (lane == 0) {
        uint4 z = {0u, 0u, 0u, 0u};
        *(uint4*)(g_wbf + (size_t)j * ASTR + Dd) = z;
    }
}

// no-op kernel: keeps the profiler's 4th-launch capture slot on fix_ties
__global__ void dummy_k() {}

__device__ __forceinline__ void upd(float s, int j, float& b1, float& b2, int& i1) {
    if (s < b1) { b2 = b1; b1 = s; i1 = j; }
    else if (s < b2) b2 = s;
}

// ---- main fused kernel (UNCHANGED 274.5us champion) ----
__global__ __launch_bounds__(256, 2) void vq_main(const float* __restrict__ x,
                                                  const float* __restrict__ pw,
                                                  float* __restrict__ out) {
    extern __shared__ char smem[];
    const u32 sb = smem_u32(smem);
    float* wns  = (float*)(smem + SM_WNS);
    float* rv   = (float*)(smem + SM_RV);
    float* r2s  = (float*)(smem + SM_R2);
    int*   ris  = (int*)  (smem + SM_RI);
    int*   idxs = (int*)  (smem + SM_IDX);
    int*   flg  = (int*)  (smem + SM_FLG);

    const int tid = threadIdx.x;
    const int wid = tid >> 5;
    const int lane = tid & 31;
    const int bm = blockIdx.x * BM;

    {
        const char* src = (const char*)g_wbf;
        for (int e = tid; e < CHB / 16; e += 256)
            cp16(sb + SM_B + e * 16, src + e * 16);
        CP_COMMIT();
    }
    for (int e = tid; e < NPROTO; e += 256) wns[e] = g_wn[e];
    stage_bf16((__nv_bfloat16*)(smem + SM_A), (const float4*)x, (size_t)bm, tid);
    CP_WAIT0();
    __syncthreads();

    const u32 arow = wid * 16 + ((lane >> 3) & 1) * 8 + (lane & 7);
    const u32 akoff = (lane >> 4) * 8;
    const u32 brow = ((lane >> 4) * 8 + (lane & 7));
    const u32 bkoff = ((lane >> 3) & 1) * 8;

    u32 A[16][4];
    #pragma unroll
    for (int kt = 0; kt < 16; kt++)
        ldm_x4(sb + SM_A + (arow * ASTR + kt * 16 + akoff) * 2,
               A[kt][0], A[kt][1], A[kt][2], A[kt][3]);

    const int th = lane & 3;
    float b1a = 3.0e38f, b2a = 3.0e38f; int i1a = 0;
    float b1b = 3.0e38f, b2b = 3.0e38f; int i1b = 0;

    for (int c = 0; c < NCH; c++) {
        if (c < NCH - 1) {
            const char* src = (const char*)g_wbf + (size_t)(c + 1) * CHB;
            u32 dst = sb + SM_B + ((c + 1) & 1) * CHB;
            for (int e = tid; e < CHB / 16; e += 256)
                cp16(dst + e * 16, src + e * 16);
            CP_COMMIT();
        }
        float acc[4][4];
        #pragma unroll
        for (int i = 0; i < 4; i++)
            #pragma unroll
            for (int q = 0; q < 4; q++) acc[i][q] = 0.f;

        const u32 bbase = sb + SM_B + (c & 1) * CHB;
        #pragma unroll
        for (int kt = 0; kt < 16; kt++) {
            #pragma unroll
            for (int ni = 0; ni < 2; ni++) {
                u32 c0, c1, c2, c3;
                u32 addr = bbase + (((ni * 16 + brow) * ASTR) + kt * 16 + bkoff) * 2;
                ldm_x4(addr, c0, c1, c2, c3);
                mma_bf16(acc[ni * 2],     A[kt][0], A[kt][1], A[kt][2], A[kt][3], c0, c1);
                mma_bf16(acc[ni * 2 + 1], A[kt][0], A[kt][1], A[kt][2], A[kt][3], c2, c3);
            }
        }
        #pragma unroll
        for (int i = 0; i < 4; i++) {
            const int jb = c * CHP + i * 8 + th * 2;
            float s;
            s = fmaf(-2.f, acc[i][0], wns[jb]);     upd(s, jb,     b1a, b2a, i1a);
            s = fmaf(-2.f, acc[i][1], wns[jb + 1]); upd(s, jb + 1, b1a, b2a, i1a);
            s = fmaf(-2.f, acc[i][2], wns[jb]);     upd(s, jb,     b1b, b2b, i1b);
            s = fmaf(-2.f, acc[i][3], wns[jb + 1]); upd(s, jb + 1, b1b, b2b, i1b);
        }
        if (c < NCH - 1) { CP_WAIT0(); __syncthreads(); }
    }

    #pragma unroll
    for (int off = 1; off <= 2; off <<= 1) {
        float ov, o2; int oi;
        ov = __shfl_xor_sync(0xffffffffu, b1a, off);
        o2 = __shfl_xor_sync(0xffffffffu, b2a, off);
        oi = __shfl_xor_sync(0xffffffffu, i1a, off);
        if (ov < b1a || (ov == b1a && oi < i1a)) { b2a = fminf(b1a, o2); b1a = ov; i1a = oi; }
        else b2a = fminf(b2a, ov);
        ov = __shfl_xor_sync(0xffffffffu, b1b, off);
        o2 = __shfl_xor_sync(0xffffffffu, b2b, off);
        oi = __shfl_xor_sync(0xffffffffu, i1b, off);
        if (ov < b1b || (ov == b1b && oi < i1b)) { b2b = fminf(b1b, o2); b1b = ov; i1b = oi; }
        else b2b = fminf(b2b, ov);
    }
    if (th == 0) {
        int g = lane >> 2;
        int ra = wid * 16 + g, rb = ra + 8;
        rv[ra] = b1a; r2s[ra] = b2a; ris[ra] = i1a;
        rv[rb] = b1b; r2s[rb] = b2b; ris[rb] = i1b;
    }
    __syncthreads();
    if (tid < BM) {
        float B1 = rv[tid], B2 = r2s[tid];
        int I1 = ris[tid];
        idxs[tid] = I1;
        int f = (B2 - B1 < TAU) ? 1 : 0;
        flg[tid] = f;
        if (f) g_flaglist[atomicAdd(&g_nflag, 1)] = bm + tid;
    }
    __syncthreads();

    float lsum = 0.f;
    float4* outP = (float4*)out;
    float4* outX = outP + TDTOT / 4;
    const float4* w4 = (const float4*)pw;
    const float4* x4 = (const float4*)x;
    for (int e = tid; e < BM * 64; e += 256) {
        int r = e >> 6, c4 = e & 63;
        int j = idxs[r];
        float4 wv = __ldg(&w4[(size_t)j * 64 + c4]);
        float4 xv = x4[(size_t)(bm + r) * 64 + c4];
        size_t o = (size_t)(bm + r) * 64 + c4;
        float4 dx;
        dx.x = xv.x - wv.x; dx.y = xv.y - wv.y;
        dx.z = xv.z - wv.z; dx.w = xv.w - wv.w;
        __stcs(&outP[o], wv);
        __stcs(&outX[o], dx);
        if (!flg[r]) lsum += dx.x * dx.x + dx.y * dx.y + dx.z * dx.z + dx.w * dx.w;
    }
    #pragma unroll
    for (int s = 16; s > 0; s >>= 1) lsum += __shfl_down_sync(0xffffffffu, lsum, s);
    __syncthreads();
    if ((tid & 31) == 0) rv[wid] = lsum;
    __syncthreads();
    if (tid == 0) {
        float t = 0.f;
        #pragma unroll
        for (int w = 0; w < 8; w++) t += rv[w];
        g_partials[blockIdx.x] = t;
    }
}

// ---- phase 2: warp-per-token; FIXB=8 amortization + float4-packed W ----
__global__ __launch_bounds__(256) void fix_ties(const float* __restrict__ x,
                                                const float* __restrict__ pw,
                                                float* __restrict__ out) {
    __shared__ float xs[FIXB][Dd];
    __shared__ float sc[FIXB][NPROTO];
    __shared__ int clist[FIXB][MAXC];

    const int tid = threadIdx.x;
    const int lane = tid & 31, wrp = tid >> 5;
    const int nf = g_nflag;
    const int nb = (nf + FIXB - 1) / FIXB;

    for (int b = blockIdx.x; b < nb; b += gridDim.x) {
        const int base = b * FIXB;
        const int m = min(FIXB, nf - base);
        __syncthreads();
        for (int e = tid; e < m * Dd; e += 256) {
            int i = e >> 8, k = e & 255;
            xs[i][k] = x[(size_t)g_flaglist[base + i] * Dd + k];
        }
        __syncthreads();

        // tier-1: thread t scores protos t, t+256; W via g_wt4[k4][j]
        // (coalesced float4, 128 LDG.128/thread). k-ascending accumulation
        // per proto — bit-identical scores to all prior rounds.
        float a0[FIXB], a1[FIXB];
        #pragma unroll
        for (int i = 0; i < FIXB; i++) { a0[i] = 0.f; a1[i] = 0.f; }
        for (int k4 = 0; k4 < 64; k4++) {
            float4 w0 = g_wt4[(size_t)k4 * NPROTO + tid];
            float4 w1 = g_wt4[(size_t)k4 * NPROTO + tid + 256];
            #pragma unroll
            for (int i = 0; i < FIXB; i++) {
                float4 xv = *(const float4*)&xs[i][k4 * 4];
                a0[i] = fmaf(xv.x, w0.x, a0[i]);
                a0[i] = fmaf(xv.y, w0.y, a0[i]);
                a0[i] = fmaf(xv.z, w0.z, a0[i]);
                a0[i] = fmaf(xv.w, w0.w, a0[i]);
                a1[i] = fmaf(xv.x, w1.x, a1[i]);
                a1[i] = fmaf(xv.y, w1.y, a1[i]);
                a1[i] = fmaf(xv.z, w1.z, a1[i]);
                a1[i] = fmaf(xv.w, w1.w, a1[i]);
            }
        }
        float wn0 = g_wn[tid], wn1 = g_wn[tid + 256];
        #pragma unroll
        for (int i = 0; i < FIXB; i++) {
            sc[i][tid] = wn0 - 2.f * a0[i];
            sc[i][tid + 256] = wn1 - 2.f * a1[i];
        }
        __syncthreads();

        // warp w resolves token w — fully warp-local
        if (wrp < m) {
            const int w = wrp;
            float lmin = 3.0e38f;
            #pragma unroll
            for (int q = 0; q < 16; q++)
                lmin = fminf(lmin, sc[w][lane * 16 + q]);
            #pragma unroll
            for (int off = 16; off > 0; off >>= 1)
                lmin = fminf(lmin, __shfl_xor_sync(0xffffffffu, lmin, off));
            const float thresh = lmin + CAND_CUT;

            int cbase = 0;
            #pragma unroll
            for (int q = 0; q < 16; q++) {
                int j = lane * 16 + q;
                bool pred = sc[w][j] < thresh;
                u32 mask = __ballot_sync(0xffffffffu, pred);
                if (pred) {
                    int pos = cbase + __popc(mask & ((1u << lane) - 1u));
                    if (pos < MAXC) clist[w][pos] = j;
                }
                cbase += __popc(mask);
            }
            const int nc = min(cbase, MAXC);
            __syncwarp();

            double px = 0.0;
            #pragma unroll
            for (int e = 0; e < 8; e++) {
                double v = (double)xs[w][lane * 8 + e];
                px += v * v;
            }
            #pragma unroll
            for (int off = 16; off > 0; off >>= 1)
                px += __shfl_xor_sync(0xffffffffu, px, off);
            const float sx = (float)px;

            float bv = 3.0e38f; int bj = 0x7fffffff;
            for (int c = 0; c < nc; c++) {
                int j = clist[w][c];
                const float* wr = pw + (size_t)j * Dd;
                double d = 0.0;
                #pragma unroll
                for (int e = 0; e < 8; e++)
                    d += (double)xs[w][lane + 32 * e] * (double)wr[lane + 32 * e];
                #pragma unroll
                for (int off = 16; off > 0; off >>= 1)
                    d += __shfl_xor_sync(0xffffffffu, d, off);
                float dist = __fsub_rn(__fadd_rn(sx, g_wn[j]), 2.0f * (float)d);
                if (dist < bv || (dist == bv && j < bj)) { bv = dist; bj = j; }
            }
            const int jb = (nc > 0) ? bj : 0;

            const int t = g_flaglist[base + w];
            float ls = 0.f;
            for (int e = lane; e < Dd; e += 32) {
                float wv = pw[(size_t)jb * Dd + e];
                float xv2 = xs[w][e];
                out[(size_t)t * Dd + e] = wv;
                float dx = xv2 - wv;
                out[TDTOT + (size_t)t * Dd + e] = dx;
                ls += dx * dx;
            }
            #pragma unroll
            for (int off = 16; off > 0; off >>= 1)
                ls += __shfl_xor_sync(0xffffffffu, ls, off);
            if (lane == 0) g_extra[t] = ls;
        }
    }
}

__global__ void reduce_extra() {
    __shared__ float s[256];
    int tid = threadIdx.x;
    int base = blockIdx.x * 512;
    s[tid] = g_extra[base + tid] + g_extra[base + 256 + tid];
    __syncthreads();
    for (int st = 128; st > 0; st >>= 1) {
        if (tid < st) s[tid] += s[tid + st];
        __syncthreads();
    }
    if (tid == 0) g_epart[blockIdx.x] = s[0];
}

__global__ void finalize_loss(float* __restrict__ out) {
    __shared__ float s[256];
    int tid = threadIdx.x;
    float v = 0.f;
    for (int t = tid; t < NBLK; t += 256) v += g_partials[t];
    if (tid < 256) v += g_epart[tid];
    s[tid] = v;
    __syncthreads();
    for (int st = 128; st > 0; st >>= 1) {
        if (tid < st) s[tid] += s[tid + st];
        __syncthreads();
    }
    if (tid == 0) out[2 * TDTOT] = s[0] * (1.25f / (float)TDTOT);
}

extern "C" void kernel_launch(void* const* d_in, const int* in_sizes, int n_in,
                              void* d_out, int out_size) {
    const float* x  = (const float*)d_in[0];
    const float* pw = (const float*)d_in[1];
    float* out = (float*)d_out;

    cudaFuncSetAttribute(vq_main, cudaFuncAttributeMaxDynamicSharedMemorySize, SMEMB);
    wnwt_kernel<<<64, 256>>>(pw);
    dummy_k<<<1, 32>>>();      // capture slot = 4th launch -> fix_ties
    vq_main<<<NBLK, 256, SMEMB>>>(x, pw, out);
    fix_ties<<<512, 256>>>(x, pw, out);
    reduce_extra<<<256, 256>>>();
    finalize_loss<<<1, 256>>>(out);
}